// round 8
// baseline (speedup 1.0000x reference)
#include <cuda_runtime.h>
#include <cstdint>
#include <cstddef>

#define TT 256
#define BB 64
#define HH 512
#define G6 3072
#define G5 2560
#define LAYER_W_STRIDE (512*3072 + 512*2560)   /* 2883584 */
#define WHH_OFF (512*3072)                      /* 1572864 */
#define NCTA 128

// smem layout for lstm kernel (floats)
#define OFF_W 0            /* 4*5*512   = 10240 floats (40KB)  */
#define OFF_H 10240        /* 512*64    = 32768 floats (128KB) */
#define OFF_R 43008        /* 8*32*42   = 10752 floats (42KB)  */
#define SMEM_LSTM ((10240 + 32768 + 10752) * 4)   /* 215040 B */

// ---------------- device scratch (static, no runtime alloc) ----------------
__device__ float g_xt[(size_t)TT*HH*BB];          // layer input  [t][k][b]
__device__ float g_yt[(size_t)TT*HH*BB];          // layer output [t][k][b]
__device__ float g_xr[(size_t)TT*HH*BB];          // reversed input
__device__ float g_xi[(size_t)TT*G6*BB];          // xi [t][g][b]
__device__ float g_h0[HH*BB];                     // h [k][b]
__device__ float g_h1[HH*BB];
__device__ float g_wt[(size_t)4*G5*HH];           // W_hh packed [l][hid*5+g][k]
__device__ unsigned g_bar[2];                     // [0]=count (monotonic), [1]=epoch

// ---------------- f32x2 packed FMA (sm_100+) ----------------
__device__ __forceinline__ float2 ffma2(float2 a, float2 b, float2 c) {
    union U { float2 f; unsigned long long u; };
    U A, B, C, D;
    A.f = a; B.f = b; C.f = c;
    asm("fma.rn.f32x2 %0, %1, %2, %3;" : "=l"(D.u) : "l"(A.u), "l"(B.u), "l"(C.u));
    return D.f;
}

__device__ __forceinline__ float sigmoidf_(float x) {
    return 1.0f / (1.0f + __expf(-x));
}

__device__ __forceinline__ unsigned atom_add_release_gpu(unsigned* p, unsigned v) {
    unsigned old;
    asm volatile("atom.release.gpu.add.u32 %0, [%1], %2;"
                 : "=r"(old) : "l"(p), "r"(v) : "memory");
    return old;
}
__device__ __forceinline__ void red_add_release_gpu(unsigned* p, unsigned v) {
    asm volatile("red.release.gpu.add.u32 [%0], %1;"
                 :: "l"(p), "r"(v) : "memory");
}
__device__ __forceinline__ unsigned ld_acquire_gpu(const unsigned* p) {
    unsigned v;
    asm volatile("ld.acquire.gpu.u32 %0, [%1];" : "=r"(v) : "l"(p) : "memory");
    return v;
}

// ---------------- prep: (B,T,K) -> [t][k][b], masked ----------------
__global__ void prep_kernel(const float* __restrict__ in, const int* __restrict__ len) {
    int idx = blockIdx.x * blockDim.x + threadIdx.x;
    if (idx >= TT*HH*BB) return;
    int b = idx & 63;
    int k = (idx >> 6) & 511;
    int t = idx >> 15;
    float v = 0.f;
    if (t < len[b]) v = in[((size_t)b*TT + t)*HH + k];
    g_xt[idx] = v;
}

// ---------------- reverse gather: xr[t][k][b] = xt[t'][k][b] ----------------
__global__ void reverse_kernel(const float* __restrict__ xt, float* __restrict__ xr,
                               const int* __restrict__ len) {
    int idx = blockIdx.x * blockDim.x + threadIdx.x;
    if (idx >= TT*HH*BB) return;
    int b = idx & 63;
    int k = (idx >> 6) & 511;
    int t = idx >> 15;
    int L = len[b];
    int tp = (t < L) ? (L - 1 - t) : t;
    xr[idx] = xt[((size_t)tp*HH + k)*BB + b];
}

// ---------------- pack W_hh[k][g*512+hid] -> wt[l][(hid*5+g)][k] ----------------
__global__ void packw_kernel(const float* __restrict__ weight) {
    int idx = blockIdx.x * blockDim.x + threadIdx.x;
    if (idx >= 4*HH*G5) return;
    int col = idx % G5;
    int k   = (idx / G5) % HH;
    int l   = idx / (G5*HH);
    int hid = col & 511, g = col >> 9;
    float v = weight[(size_t)l*LAYER_W_STRIDE + WHH_OFF + (size_t)k*G5 + col];
    g_wt[(size_t)l*(G5*HH) + (size_t)((hid*5 + g) << 9) + k] = v;
}

// ---------------- xi GEMM: xi[t][g][b] = sum_k W[k][g] * X[t][k][b] ----------------
__device__ __forceinline__ int bskew(int c) { return c + ((c >> 5) << 2); }

__global__ __launch_bounds__(256, 2)
void gemm_xi_kernel(const float* __restrict__ X, const float* __restrict__ W,
                    float* __restrict__ XI)
{
    __shared__ float As[8][128];
    __shared__ float Bs[8][144];    // skewed width: bskew(124)+3 = 139 < 144
    int tid = threadIdx.x;
    int mBase = blockIdx.x * 128;
    int gBase = blockIdx.y * 128;

    float2 acc[8][4];
    #pragma unroll
    for (int i = 0; i < 8; i++)
        #pragma unroll
        for (int j = 0; j < 4; j++) acc[i][j] = make_float2(0.f, 0.f);

    int sk  = tid >> 5;
    int sc4 = (tid & 31) * 4;
    int ty8 = (tid >> 4) * 8;
    int tx8 = (tid & 15) * 8;

    int m4 = mBase + sc4;
    const float* bsrc = X + ((size_t)(m4 >> 6) * HH) * BB + (m4 & 63);
    const float* asrc = W + gBase + sc4;
    int bsw = bskew(sc4);
    int c0 = bskew(tx8), c1 = bskew(tx8 + 4);

    for (int k0 = 0; k0 < 512; k0 += 8) {
        float4 av = *(const float4*)(asrc + (size_t)(k0 + sk)*G6);
        float4 bv = *(const float4*)(bsrc + (size_t)(k0 + sk)*BB);
        *(float4*)&As[sk][sc4] = av;
        *(float4*)&Bs[sk][bsw] = bv;
        __syncthreads();
        #pragma unroll
        for (int kk = 0; kk < 8; kk++) {
            float4 a0 = *(float4*)&As[kk][ty8];
            float4 a1 = *(float4*)&As[kk][ty8+4];
            float4 b0 = *(float4*)&Bs[kk][c0];
            float4 b1 = *(float4*)&Bs[kk][c1];
            float  ar[8] = {a0.x,a0.y,a0.z,a0.w,a1.x,a1.y,a1.z,a1.w};
            float2 br[4] = {make_float2(b0.x,b0.y), make_float2(b0.z,b0.w),
                            make_float2(b1.x,b1.y), make_float2(b1.z,b1.w)};
            #pragma unroll
            for (int i = 0; i < 8; i++) {
                float2 ad = make_float2(ar[i], ar[i]);
                #pragma unroll
                for (int jp = 0; jp < 4; jp++)
                    acc[i][jp] = ffma2(ad, br[jp], acc[i][jp]);
            }
        }
        __syncthreads();
    }

    int m0 = mBase + tx8;
    int t  = m0 >> 6;
    int b0 = m0 & 63;
    #pragma unroll
    for (int i = 0; i < 8; i++) {
        float* o = XI + ((size_t)t*G6 + gBase + ty8 + i)*BB + b0;
        *(float4*)(o)     = make_float4(acc[i][0].x, acc[i][0].y, acc[i][1].x, acc[i][1].y);
        *(float4*)(o + 4) = make_float4(acc[i][2].x, acc[i][2].y, acc[i][3].x, acc[i][3].y);
    }
}

// ---------------- persistent per-layer recurrence ----------------
// 128 CTAs x 256 thr; CTA owns 4 hids. h staged in 4x32KB chunks, software
// pipelined (LDG of chunk c+1 issued before FMA of chunk c). Fence-free
// release/acquire grid barrier; y-store + xi prefetch in barrier shadow.
__global__ __launch_bounds__(256)
void lstm_layer_kernel(const float* __restrict__ xi_base, // [T][G6][B]
                       const float* __restrict__ wt,      // packed layer W_hh
                       const float* __restrict__ bias,    // [G5]
                       const int*   __restrict__ len,
                       float* __restrict__ hbuf0,
                       float* __restrict__ hbuf1,
                       float* __restrict__ y,             // [T][H][B]
                       int rev)
{
    extern __shared__ float smf[];
    int tid = threadIdx.x;
    int hid0 = blockIdx.x * 4;

    // FMA-phase mapping: w8 = 16-k slice within chunk, bp = batch pair
    int w8 = tid >> 5;          // 0..7
    int bp = tid & 31;          // 0..31
    // output-phase mapping
    int hl_o = tid >> 6;        // 0..3
    int b_o  = tid & 63;
    int hid_o = hid0 + hl_o;

    // one-time: weights -> smem (40KB linear)
    {
        const float4* ws = (const float4*)(wt + (size_t)hid0 * 5 * 512);
        float4* wd = (float4*)(smf + OFF_W);
        #pragma unroll
        for (int i = 0; i < 10; i++) wd[tid + i*256] = ws[tid + i*256];
    }
    float bval[5];
    #pragma unroll
    for (int g = 0; g < 5; g++) bval[g] = bias[g*512 + hid_o];
    int L = len[b_o];
    float c = 0.0f;

    const float* hin  = hbuf0;
    float*       hout = hbuf1;

    // prologue xi (s = 0)
    float xiv[6];
    #pragma unroll
    for (int g = 0; g < 6; g++)
        xiv[g] = __ldcs(xi_base + (size_t)(g*512 + hid_o)*BB + b_o);

    __syncthreads();

    for (int s = 0; s < TT; s++) {
        const float4* hs = (const float4*)hin;
        float4* hd = (float4*)(smf + OFF_H);
        float4 r[8];

        // prologue: chunk 0 stage, chunk 1 LDG in flight
        #pragma unroll
        for (int i = 0; i < 8; i++) r[i] = __ldcg(hs + tid + i*256);
        #pragma unroll
        for (int i = 0; i < 8; i++) hd[tid + i*256] = r[i];
        __syncthreads();
        #pragma unroll
        for (int i = 0; i < 8; i++) r[i] = __ldcg(hs + 2048 + tid + i*256);

        float2 acc[20];
        #pragma unroll
        for (int q = 0; q < 20; q++) acc[q] = make_float2(0.f, 0.f);

        #pragma unroll
        for (int ch = 0; ch < 4; ch++) {
            // FMA on chunk ch (LDG of chunk ch+1 outstanding)
            const float* shh = smf + OFF_H + ch*8192 + 2*bp;
            const float* shw = smf + OFF_W + ch*128 + w8*16;
            #pragma unroll
            for (int k4 = 0; k4 < 16; k4 += 4) {
                int kb = (w8*16 + k4) * 64;
                float2 hv0 = *(const float2*)(shh + kb);
                float2 hv1 = *(const float2*)(shh + kb + 64);
                float2 hv2 = *(const float2*)(shh + kb + 128);
                float2 hv3 = *(const float2*)(shh + kb + 192);
                #pragma unroll
                for (int q = 0; q < 20; q++) {
                    float4 w4 = *(const float4*)(shw + q*512 + k4);
                    acc[q] = ffma2(hv0, make_float2(w4.x, w4.x), acc[q]);
                    acc[q] = ffma2(hv1, make_float2(w4.y, w4.y), acc[q]);
                    acc[q] = ffma2(hv2, make_float2(w4.z, w4.z), acc[q]);
                    acc[q] = ffma2(hv3, make_float2(w4.w, w4.w), acc[q]);
                }
            }
            if (ch < 3) {
                // commit chunk ch+1, start LDG of chunk ch+2
                #pragma unroll
                for (int i = 0; i < 8; i++)
                    hd[(ch+1)*2048 + tid + i*256] = r[i];
                __syncthreads();
                if (ch < 2) {
                    #pragma unroll
                    for (int i = 0; i < 8; i++)
                        r[i] = __ldcg(hs + (ch+2)*2048 + tid + i*256);
                }
            }
        }

        // write partials (stride 42 avoids conflicts)
        {
            float* rb = smf + OFF_R + (w8*32 + bp)*42;
            #pragma unroll
            for (int q = 0; q < 20; q++) *(float2*)(rb + 2*q) = acc[q];
        }
        __syncthreads();

        // reduce + gates (output mapping)
        float gv[5];
        #pragma unroll
        for (int g = 0; g < 5; g++) gv[g] = xiv[g] + bval[g];
        {
            const float* rbase = smf + OFF_R + (b_o >> 1)*42 + (b_o & 1);
            #pragma unroll
            for (int w2 = 0; w2 < 8; w2++) {
                const float* p = rbase + w2*32*42;
                #pragma unroll
                for (int g = 0; g < 5; g++)
                    gv[g] += p[(hl_o*5 + g)*2];
            }
        }

        float ig = sigmoidf_(gv[0]);
        float fg = sigmoidf_(gv[1]);
        float gc = tanhf(gv[2]);
        float og = sigmoidf_(gv[3]);
        float rg = sigmoidf_(gv[4]);
        float lin = xiv[5];

        float cn, hn;
        if (s < L) {
            cn = fg*c + ig*gc;
            hn = rg*(og*tanhf(cn)) + (1.f - rg)*lin;
        } else {
            cn = 0.f; hn = 0.f;
        }
        c = cn;
        hout[hid_o*BB + b_o] = hn;       // [k][b] coalesced; must precede arrive
        int dst = rev ? ((s < L) ? (L - 1 - s) : s) : s;

        if (s != TT-1) {
            __syncthreads();   // CTA-wide: all hout STGs happen-before the release below
            if (tid == 0)
                if (atom_add_release_gpu(&g_bar[0], 1u) == (unsigned)(NCTA*(s+1)) - 1u)
                    red_add_release_gpu(&g_bar[1], 1u);

            // ---- barrier shadow: y store + next-step xi prefetch ----
            y[((size_t)dst*HH + hid_o)*BB + b_o] = hn;
            const float* xs = xi_base + (size_t)(s+1)*G6*BB;
            #pragma unroll
            for (int g = 0; g < 6; g++)
                xiv[g] = __ldcs(xs + (size_t)(g*512 + hid_o)*BB + b_o);

            if (tid == 0) {
                unsigned target = (unsigned)(s + 1);
                while (ld_acquire_gpu(&g_bar[1]) < target) __nanosleep(32);
            }
            __syncthreads();
        } else {
            y[((size_t)dst*HH + hid_o)*BB + b_o] = hn;
        }

        const float* tmp = hin; hin = hout; hout = (float*)tmp;
    }
}

// ---------------- final: [t][k][b] -> (B,T,K) ----------------
__global__ void out_kernel(const float* __restrict__ xt, float* __restrict__ out) {
    int idx = blockIdx.x * blockDim.x + threadIdx.x;
    if (idx >= TT*HH*BB) return;
    int k = idx & 511;
    int t = (idx >> 9) & 255;
    int b = idx >> 17;
    out[idx] = xt[((size_t)t*HH + k)*BB + b];
}

// ---------------- launch ----------------
extern "C" void kernel_launch(void* const* d_in, const int* in_sizes, int n_in,
                              void* d_out, int out_size)
{
    const float* inputs = nullptr;
    const float* weight = nullptr;
    const float* biasp  = nullptr;
    const int*   len    = nullptr;
    for (int i = 0; i < n_in; i++) {
        switch (in_sizes[i]) {
            case TT*BB*HH:  inputs = (const float*)d_in[i]; break;  // 8388608
            case 11534336:  weight = (const float*)d_in[i]; break;
            case 4*G5:      biasp  = (const float*)d_in[i]; break;  // 10240
            case BB:        len    = (const int*)  d_in[i]; break;  // 64
        }
    }

    float *pxt, *pyt, *pxr, *pxi, *ph0, *ph1, *pwt;
    unsigned* pbar;
    cudaGetSymbolAddress((void**)&pxt, g_xt);
    cudaGetSymbolAddress((void**)&pyt, g_yt);
    cudaGetSymbolAddress((void**)&pxr, g_xr);
    cudaGetSymbolAddress((void**)&pxi, g_xi);
    cudaGetSymbolAddress((void**)&ph0, g_h0);
    cudaGetSymbolAddress((void**)&ph1, g_h1);
    cudaGetSymbolAddress((void**)&pwt, g_wt);
    cudaGetSymbolAddress((void**)&pbar, g_bar);

    cudaFuncSetAttribute(lstm_layer_kernel,
                         cudaFuncAttributeMaxDynamicSharedMemorySize, SMEM_LSTM);

    prep_kernel<<<(TT*HH*BB + 255)/256, 256>>>(inputs, len);
    packw_kernel<<<(4*HH*G5 + 255)/256, 256>>>(weight);

    float* xin  = pxt;
    float* yout = pyt;
    for (int l = 0; l < 4; l++) {
        int rev = l & 1;
        const float* gsrc = xin;
        if (rev) {
            reverse_kernel<<<(TT*HH*BB + 255)/256, 256>>>(xin, pxr, len);
            gsrc = pxr;
        }
        gemm_xi_kernel<<<dim3(128, 24), 256>>>(
            gsrc, weight + (size_t)l*LAYER_W_STRIDE, pxi);
        cudaMemsetAsync(ph0, 0, (size_t)HH*BB*sizeof(float));
        cudaMemsetAsync(pbar, 0, 2*sizeof(unsigned));
        lstm_layer_kernel<<<NCTA, 256, SMEM_LSTM>>>(
            pxi, pwt + (size_t)l*G5*HH, biasp + (size_t)l*G5,
            len, ph0, ph1, yout, rev);
        float* tmp = xin; xin = yout; yout = tmp;
    }
    out_kernel<<<(TT*HH*BB + 255)/256, 256>>>(xin, (float*)d_out);
}

// round 9
// speedup vs baseline: 1.1113x; 1.1113x over previous
#include <cuda_runtime.h>
#include <cstdint>
#include <cstddef>

#define TT 256
#define BB 64
#define HH 512
#define G6 3072
#define G5 2560
#define LAYER_W_STRIDE (512*3072 + 512*2560)   /* 2883584 */
#define WHH_OFF (512*3072)                      /* 1572864 */
#define NCTA 128

// smem layout for lstm kernel (floats)
#define OFF_W 0            /* 4*5*512   = 10240 floats (40KB)  */
#define OFF_H 10240        /* 512*64    = 32768 floats (128KB) */
#define OFF_R 43008        /* 8*32*42   = 10752 floats (42KB)  */
#define OFF_MBAR_BYTES ((10240 + 32768 + 10752) * 4)   /* 215040 */
#define SMEM_LSTM (OFF_MBAR_BYTES + 64)                /* + 4 mbarriers */

// ---------------- device scratch (static, no runtime alloc) ----------------
__device__ float g_xt[(size_t)TT*HH*BB];          // layer input  [t][k][b]
__device__ float g_yt[(size_t)TT*HH*BB];          // layer output [t][k][b]
__device__ float g_xr[(size_t)TT*HH*BB];          // reversed input
__device__ float g_xi[(size_t)TT*G6*BB];          // xi [t][g][b]
__device__ float g_h0[HH*BB];                     // h [k][b]
__device__ float g_h1[HH*BB];
__device__ float g_wt[(size_t)4*G5*HH];           // W_hh packed [l][hid*5+g][k]
__device__ unsigned g_bar[2];                     // [0]=count (monotonic), [1]=epoch

// ---------------- helpers ----------------
__device__ __forceinline__ float2 ffma2(float2 a, float2 b, float2 c) {
    union U { float2 f; unsigned long long u; };
    U A, B, C, D;
    A.f = a; B.f = b; C.f = c;
    asm("fma.rn.f32x2 %0, %1, %2, %3;" : "=l"(D.u) : "l"(A.u), "l"(B.u), "l"(C.u));
    return D.f;
}
__device__ __forceinline__ float sigmoidf_(float x) {
    return 1.0f / (1.0f + __expf(-x));
}
__device__ __forceinline__ unsigned atom_add_release_gpu(unsigned* p, unsigned v) {
    unsigned old;
    asm volatile("atom.release.gpu.add.u32 %0, [%1], %2;"
                 : "=r"(old) : "l"(p), "r"(v) : "memory");
    return old;
}
__device__ __forceinline__ void red_add_release_gpu(unsigned* p, unsigned v) {
    asm volatile("red.release.gpu.add.u32 [%0], %1;"
                 :: "l"(p), "r"(v) : "memory");
}
__device__ __forceinline__ unsigned ld_acquire_gpu(const unsigned* p) {
    unsigned v;
    asm volatile("ld.acquire.gpu.u32 %0, [%1];" : "=r"(v) : "l"(p) : "memory");
    return v;
}
__device__ __forceinline__ unsigned smem_u32(const void* p) {
    unsigned a;
    asm("{ .reg .u64 t; cvta.to.shared.u64 t, %1; cvt.u32.u64 %0, t; }"
        : "=r"(a) : "l"(p));
    return a;
}
__device__ __forceinline__ void mbar_init(unsigned a, unsigned cnt) {
    asm volatile("mbarrier.init.shared.b64 [%0], %1;" :: "r"(a), "r"(cnt) : "memory");
}
__device__ __forceinline__ void mbar_expect_tx(unsigned a, unsigned bytes) {
    asm volatile("mbarrier.arrive.expect_tx.shared.b64 _, [%0], %1;"
                 :: "r"(a), "r"(bytes) : "memory");
}
__device__ __forceinline__ void bulk_g2s(unsigned dst, const void* src,
                                         unsigned bytes, unsigned mbar) {
    asm volatile("cp.async.bulk.shared::cluster.global.mbarrier::complete_tx::bytes "
                 "[%0], [%1], %2, [%3];"
                 :: "r"(dst), "l"(src), "r"(bytes), "r"(mbar) : "memory");
}
__device__ __forceinline__ void mbar_wait_parity(unsigned a, unsigned phase) {
    unsigned done;
    asm volatile(
        "{\n\t.reg .pred p;\n\t"
        "mbarrier.try_wait.parity.acquire.cta.shared::cta.b64 p, [%1], %2;\n\t"
        "selp.b32 %0, 1, 0, p;\n\t}"
        : "=r"(done) : "r"(a), "r"(phase) : "memory");
    if (!done) {
        asm volatile(
            "{\n\t.reg .pred P1;\n\t"
            "WL_%=:\n\t"
            "mbarrier.try_wait.parity.acquire.cta.shared::cta.b64 P1, [%0], %1, 0x989680;\n\t"
            "@P1 bra.uni WD_%=;\n\t"
            "bra.uni WL_%=;\n\t"
            "WD_%=:\n\t}"
            :: "r"(a), "r"(phase) : "memory");
    }
}

// ---------------- prep: (B,T,K) -> [t][k][b], masked ----------------
__global__ void prep_kernel(const float* __restrict__ in, const int* __restrict__ len) {
    int idx = blockIdx.x * blockDim.x + threadIdx.x;
    if (idx >= TT*HH*BB) return;
    int b = idx & 63;
    int k = (idx >> 6) & 511;
    int t = idx >> 15;
    float v = 0.f;
    if (t < len[b]) v = in[((size_t)b*TT + t)*HH + k];
    g_xt[idx] = v;
}

// ---------------- reverse gather ----------------
__global__ void reverse_kernel(const float* __restrict__ xt, float* __restrict__ xr,
                               const int* __restrict__ len) {
    int idx = blockIdx.x * blockDim.x + threadIdx.x;
    if (idx >= TT*HH*BB) return;
    int b = idx & 63;
    int k = (idx >> 6) & 511;
    int t = idx >> 15;
    int L = len[b];
    int tp = (t < L) ? (L - 1 - t) : t;
    xr[idx] = xt[((size_t)tp*HH + k)*BB + b];
}

// ---------------- pack W_hh[k][g*512+hid] -> wt[l][(hid*5+g)][k] ----------------
__global__ void packw_kernel(const float* __restrict__ weight) {
    int idx = blockIdx.x * blockDim.x + threadIdx.x;
    if (idx >= 4*HH*G5) return;
    int col = idx % G5;
    int k   = (idx / G5) % HH;
    int l   = idx / (G5*HH);
    int hid = col & 511, g = col >> 9;
    float v = weight[(size_t)l*LAYER_W_STRIDE + WHH_OFF + (size_t)k*G5 + col];
    g_wt[(size_t)l*(G5*HH) + (size_t)((hid*5 + g) << 9) + k] = v;
}

// ---------------- xi GEMM (unchanged from R7/R8 passing version) ----------------
__device__ __forceinline__ int bskew(int c) { return c + ((c >> 5) << 2); }

__global__ __launch_bounds__(256, 2)
void gemm_xi_kernel(const float* __restrict__ X, const float* __restrict__ W,
                    float* __restrict__ XI)
{
    __shared__ float As[8][128];
    __shared__ float Bs[8][144];
    int tid = threadIdx.x;
    int mBase = blockIdx.x * 128;
    int gBase = blockIdx.y * 128;

    float2 acc[8][4];
    #pragma unroll
    for (int i = 0; i < 8; i++)
        #pragma unroll
        for (int j = 0; j < 4; j++) acc[i][j] = make_float2(0.f, 0.f);

    int sk  = tid >> 5;
    int sc4 = (tid & 31) * 4;
    int ty8 = (tid >> 4) * 8;
    int tx8 = (tid & 15) * 8;

    int m4 = mBase + sc4;
    const float* bsrc = X + ((size_t)(m4 >> 6) * HH) * BB + (m4 & 63);
    const float* asrc = W + gBase + sc4;
    int bsw = bskew(sc4);
    int c0 = bskew(tx8), c1 = bskew(tx8 + 4);

    for (int k0 = 0; k0 < 512; k0 += 8) {
        float4 av = *(const float4*)(asrc + (size_t)(k0 + sk)*G6);
        float4 bv = *(const float4*)(bsrc + (size_t)(k0 + sk)*BB);
        *(float4*)&As[sk][sc4] = av;
        *(float4*)&Bs[sk][bsw] = bv;
        __syncthreads();
        #pragma unroll
        for (int kk = 0; kk < 8; kk++) {
            float4 a0 = *(float4*)&As[kk][ty8];
            float4 a1 = *(float4*)&As[kk][ty8+4];
            float4 b0 = *(float4*)&Bs[kk][c0];
            float4 b1 = *(float4*)&Bs[kk][c1];
            float  ar[8] = {a0.x,a0.y,a0.z,a0.w,a1.x,a1.y,a1.z,a1.w};
            float2 br[4] = {make_float2(b0.x,b0.y), make_float2(b0.z,b0.w),
                            make_float2(b1.x,b1.y), make_float2(b1.z,b1.w)};
            #pragma unroll
            for (int i = 0; i < 8; i++) {
                float2 ad = make_float2(ar[i], ar[i]);
                #pragma unroll
                for (int jp = 0; jp < 4; jp++)
                    acc[i][jp] = ffma2(ad, br[jp], acc[i][jp]);
            }
        }
        __syncthreads();
    }

    int m0 = mBase + tx8;
    int t  = m0 >> 6;
    int b0 = m0 & 63;
    #pragma unroll
    for (int i = 0; i < 8; i++) {
        float* o = XI + ((size_t)t*G6 + gBase + ty8 + i)*BB + b0;
        *(float4*)(o)     = make_float4(acc[i][0].x, acc[i][0].y, acc[i][1].x, acc[i][1].y);
        *(float4*)(o + 4) = make_float4(acc[i][2].x, acc[i][2].y, acc[i][3].x, acc[i][3].y);
    }
}

// ---------------- persistent per-layer recurrence ----------------
// 128 CTAs x 256 thr; CTA owns 4 hids. h staged via cp.async.bulk (4x32KB
// chunks, per-chunk mbarrier); FMA warps wait parity per chunk — no
// thread-driven staging, no per-chunk syncthreads. Fence-free monotonic
// release/acquire grid barrier; y store + xi prefetch in barrier shadow.
__global__ __launch_bounds__(256)
void lstm_layer_kernel(const float* __restrict__ xi_base, // [T][G6][B]
                       const float* __restrict__ wt,      // packed layer W_hh
                       const float* __restrict__ bias,    // [G5]
                       const int*   __restrict__ len,
                       float* __restrict__ hbuf0,
                       float* __restrict__ hbuf1,
                       float* __restrict__ y,             // [T][H][B]
                       int rev)
{
    extern __shared__ float smf[];
    int tid = threadIdx.x;
    int hid0 = blockIdx.x * 4;

    unsigned smbase = smem_u32(smf);
    unsigned mbar0  = smbase + OFF_MBAR_BYTES;
    unsigned hdst0  = smbase + OFF_H * 4;

    // FMA-phase mapping
    int w8 = tid >> 5;          // 16-k slice within 128-k chunk
    int bp = tid & 31;          // batch pair
    // output-phase mapping
    int hl_o = tid >> 6;
    int b_o  = tid & 63;
    int hid_o = hid0 + hl_o;

    // one-time: weights -> smem (40KB linear)
    {
        const float4* ws = (const float4*)(wt + (size_t)hid0 * 5 * 512);
        float4* wd = (float4*)(smf + OFF_W);
        #pragma unroll
        for (int i = 0; i < 10; i++) wd[tid + i*256] = ws[tid + i*256];
    }
    if (tid == 0) {
        #pragma unroll
        for (int c = 0; c < 4; c++) mbar_init(mbar0 + 8*c, 1);
    }
    float bval[5];
    #pragma unroll
    for (int g = 0; g < 5; g++) bval[g] = bias[g*512 + hid_o];
    int L = len[b_o];
    float c = 0.0f;

    const float* hin  = hbuf0;
    float*       hout = hbuf1;

    // prologue xi (s = 0)
    float xiv[6];
    #pragma unroll
    for (int g = 0; g < 6; g++)
        xiv[g] = __ldcs(xi_base + (size_t)(g*512 + hid_o)*BB + b_o);

    __syncthreads();                      // weights + mbarrier init visible
    asm volatile("fence.proxy.async.shared::cta;" ::: "memory");

    // stage step 0
    if (tid == 0) {
        #pragma unroll
        for (int ch = 0; ch < 4; ch++) {
            mbar_expect_tx(mbar0 + 8*ch, 32768u);
            bulk_g2s(hdst0 + ch*32768u, hin + ch*8192, 32768u, mbar0 + 8*ch);
        }
    }

    for (int s = 0; s < TT; s++) {
        unsigned phase = (unsigned)(s & 1);

        float2 acc[20];
        #pragma unroll
        for (int q = 0; q < 20; q++) acc[q] = make_float2(0.f, 0.f);

        #pragma unroll
        for (int ch = 0; ch < 4; ch++) {
            mbar_wait_parity(mbar0 + 8*ch, phase);
            const float* shh = smf + OFF_H + ch*8192 + 2*bp;
            const float* shw = smf + OFF_W + ch*128 + w8*16;
            #pragma unroll
            for (int k4 = 0; k4 < 16; k4 += 4) {
                int kb = (w8*16 + k4) * 64;
                float2 hv0 = *(const float2*)(shh + kb);
                float2 hv1 = *(const float2*)(shh + kb + 64);
                float2 hv2 = *(const float2*)(shh + kb + 128);
                float2 hv3 = *(const float2*)(shh + kb + 192);
                #pragma unroll
                for (int q = 0; q < 20; q++) {
                    float4 w4 = *(const float4*)(shw + q*512 + k4);
                    acc[q] = ffma2(hv0, make_float2(w4.x, w4.x), acc[q]);
                    acc[q] = ffma2(hv1, make_float2(w4.y, w4.y), acc[q]);
                    acc[q] = ffma2(hv2, make_float2(w4.z, w4.z), acc[q]);
                    acc[q] = ffma2(hv3, make_float2(w4.w, w4.w), acc[q]);
                }
            }
        }

        // write partials (stride 42 avoids conflicts)
        {
            float* rb = smf + OFF_R + (w8*32 + bp)*42;
            #pragma unroll
            for (int q = 0; q < 20; q++) *(float2*)(rb + 2*q) = acc[q];
        }
        __syncthreads();                              // sync A

        // reduce + gates (output mapping)
        float gv[5];
        #pragma unroll
        for (int g = 0; g < 5; g++) gv[g] = xiv[g] + bval[g];
        {
            const float* rbase = smf + OFF_R + (b_o >> 1)*42 + (b_o & 1);
            #pragma unroll
            for (int w2 = 0; w2 < 8; w2++) {
                const float* p = rbase + w2*32*42;
                #pragma unroll
                for (int g = 0; g < 5; g++)
                    gv[g] += p[(hl_o*5 + g)*2];
            }
        }

        float ig = sigmoidf_(gv[0]);
        float fg = sigmoidf_(gv[1]);
        float gc = tanhf(gv[2]);
        float og = sigmoidf_(gv[3]);
        float rg = sigmoidf_(gv[4]);
        float lin = xiv[5];

        float cn, hn;
        if (s < L) {
            cn = fg*c + ig*gc;
            hn = rg*(og*tanhf(cn)) + (1.f - rg)*lin;
        } else {
            cn = 0.f; hn = 0.f;
        }
        c = cn;
        hout[hid_o*BB + b_o] = hn;                    // coalesced
        int dst = rev ? ((s < L) ? (L - 1 - s) : s) : s;

        if (s != TT-1) {
            __syncthreads();                          // sync B: all hout STGs done
            if (tid == 0)
                if (atom_add_release_gpu(&g_bar[0], 1u) == (unsigned)(NCTA*(s+1)) - 1u)
                    red_add_release_gpu(&g_bar[1], 1u);

            // barrier shadow: y store + next-step xi prefetch
            y[((size_t)dst*HH + hid_o)*BB + b_o] = hn;
            const float* xs = xi_base + (size_t)(s+1)*G6*BB;
            #pragma unroll
            for (int g = 0; g < 6; g++)
                xiv[g] = __ldcs(xs + (size_t)(g*512 + hid_o)*BB + b_o);

            // swap buffers (next hin = current hout)
            const float* hnext = hout;
            hout = (float*)hin;
            hin  = hnext;

            if (tid == 0) {
                unsigned target = (unsigned)(s + 1);
                while (ld_acquire_gpu(&g_bar[1]) < target) __nanosleep(32);
                // h for step s+1 ready at gpu scope — stage it
                #pragma unroll
                for (int ch = 0; ch < 4; ch++) {
                    mbar_expect_tx(mbar0 + 8*ch, 32768u);
                    bulk_g2s(hdst0 + ch*32768u, hin + ch*8192, 32768u, mbar0 + 8*ch);
                }
            }
            // non-leader warps proceed straight to the chunk-0 mbarrier wait
        } else {
            y[((size_t)dst*HH + hid_o)*BB + b_o] = hn;
        }
    }
}

// ---------------- final: [t][k][b] -> (B,T,K) ----------------
__global__ void out_kernel(const float* __restrict__ xt, float* __restrict__ out) {
    int idx = blockIdx.x * blockDim.x + threadIdx.x;
    if (idx >= TT*HH*BB) return;
    int k = idx & 511;
    int t = (idx >> 9) & 255;
    int b = idx >> 17;
    out[idx] = xt[((size_t)t*HH + k)*BB + b];
}

// ---------------- launch ----------------
extern "C" void kernel_launch(void* const* d_in, const int* in_sizes, int n_in,
                              void* d_out, int out_size)
{
    const float* inputs = nullptr;
    const float* weight = nullptr;
    const float* biasp  = nullptr;
    const int*   len    = nullptr;
    for (int i = 0; i < n_in; i++) {
        switch (in_sizes[i]) {
            case TT*BB*HH:  inputs = (const float*)d_in[i]; break;  // 8388608
            case 11534336:  weight = (const float*)d_in[i]; break;
            case 4*G5:      biasp  = (const float*)d_in[i]; break;  // 10240
            case BB:        len    = (const int*)  d_in[i]; break;  // 64
        }
    }

    float *pxt, *pyt, *pxr, *pxi, *ph0, *ph1, *pwt;
    unsigned* pbar;
    cudaGetSymbolAddress((void**)&pxt, g_xt);
    cudaGetSymbolAddress((void**)&pyt, g_yt);
    cudaGetSymbolAddress((void**)&pxr, g_xr);
    cudaGetSymbolAddress((void**)&pxi, g_xi);
    cudaGetSymbolAddress((void**)&ph0, g_h0);
    cudaGetSymbolAddress((void**)&ph1, g_h1);
    cudaGetSymbolAddress((void**)&pwt, g_wt);
    cudaGetSymbolAddress((void**)&pbar, g_bar);

    cudaFuncSetAttribute(lstm_layer_kernel,
                         cudaFuncAttributeMaxDynamicSharedMemorySize, SMEM_LSTM);

    prep_kernel<<<(TT*HH*BB + 255)/256, 256>>>(inputs, len);
    packw_kernel<<<(4*HH*G5 + 255)/256, 256>>>(weight);

    float* xin  = pxt;
    float* yout = pyt;
    for (int l = 0; l < 4; l++) {
        int rev = l & 1;
        const float* gsrc = xin;
        if (rev) {
            reverse_kernel<<<(TT*HH*BB + 255)/256, 256>>>(xin, pxr, len);
            gsrc = pxr;
        }
        gemm_xi_kernel<<<dim3(128, 24), 256>>>(
            gsrc, weight + (size_t)l*LAYER_W_STRIDE, pxi);
        cudaMemsetAsync(ph0, 0, (size_t)HH*BB*sizeof(float));
        cudaMemsetAsync(pbar, 0, 2*sizeof(unsigned));
        lstm_layer_kernel<<<NCTA, 256, SMEM_LSTM>>>(
            pxi, pwt + (size_t)l*G5*HH, biasp + (size_t)l*G5,
            len, ph0, ph1, yout, rev);
        float* tmp = xin; xin = yout; yout = tmp;
    }
    out_kernel<<<(TT*HH*BB + 255)/256, 256>>>(xin, (float*)d_out);
}

// round 10
// speedup vs baseline: 1.2789x; 1.1508x over previous
#include <cuda_runtime.h>
#include <cstdint>
#include <cstddef>

#define TT 256
#define BB 64
#define HH 512
#define G6 3072
#define G5 2560
#define LAYER_W_STRIDE (512*3072 + 512*2560)   /* 2883584 */
#define WHH_OFF (512*3072)                      /* 1572864 */
#define NCTA 128

// smem layout for lstm kernel (floats)
#define OFF_W 0            /* 4*5*512   = 10240 floats (40KB)  */
#define OFF_H 10240        /* 512*64    = 32768 floats (128KB) */
#define OFF_R 43008        /* 8*32*42   = 10752 floats (42KB)  */
#define OFF_MBAR_BYTES ((10240 + 32768 + 10752) * 4)   /* 215040 */
#define SMEM_LSTM (OFF_MBAR_BYTES + 64)                /* + 4 mbarriers */

// ---------------- device scratch (static, no runtime alloc) ----------------
__device__ float g_xt[(size_t)TT*HH*BB];          // layer input  [t][k][b]
__device__ float g_yt[(size_t)TT*HH*BB];          // layer output [t][k][b]
__device__ float g_xr[(size_t)TT*HH*BB];          // reversed input
__device__ float g_xi[(size_t)TT*G6*BB];          // xi [t][g][b]
__device__ float g_h0[HH*BB];                     // h [k][b]
__device__ float g_h1[HH*BB];
__device__ float g_wt[(size_t)4*G5*HH];           // W_hh packed [l][hid*5+g][k]
__device__ unsigned g_cnt[4];                     // per-group monotonic counters

// ---------------- helpers ----------------
__device__ __forceinline__ float2 ffma2(float2 a, float2 b, float2 c) {
    union U { float2 f; unsigned long long u; };
    U A, B, C, D;
    A.f = a; B.f = b; C.f = c;
    asm("fma.rn.f32x2 %0, %1, %2, %3;" : "=l"(D.u) : "l"(A.u), "l"(B.u), "l"(C.u));
    return D.f;
}
__device__ __forceinline__ float sigmoidf_(float x) {
    return 1.0f / (1.0f + __expf(-x));
}
__device__ __forceinline__ void red_add_release_gpu(unsigned* p, unsigned v) {
    asm volatile("red.release.gpu.add.u32 [%0], %1;"
                 :: "l"(p), "r"(v) : "memory");
}
__device__ __forceinline__ unsigned ld_acquire_gpu(const unsigned* p) {
    unsigned v;
    asm volatile("ld.acquire.gpu.u32 %0, [%1];" : "=r"(v) : "l"(p) : "memory");
    return v;
}
__device__ __forceinline__ unsigned smem_u32(const void* p) {
    unsigned a;
    asm("{ .reg .u64 t; cvta.to.shared.u64 t, %1; cvt.u32.u64 %0, t; }"
        : "=r"(a) : "l"(p));
    return a;
}
__device__ __forceinline__ void mbar_init(unsigned a, unsigned cnt) {
    asm volatile("mbarrier.init.shared.b64 [%0], %1;" :: "r"(a), "r"(cnt) : "memory");
}
__device__ __forceinline__ void mbar_expect_tx(unsigned a, unsigned bytes) {
    asm volatile("mbarrier.arrive.expect_tx.shared.b64 _, [%0], %1;"
                 :: "r"(a), "r"(bytes) : "memory");
}
__device__ __forceinline__ void bulk_g2s(unsigned dst, const void* src,
                                         unsigned bytes, unsigned mbar) {
    asm volatile("cp.async.bulk.shared::cluster.global.mbarrier::complete_tx::bytes "
                 "[%0], [%1], %2, [%3];"
                 :: "r"(dst), "l"(src), "r"(bytes), "r"(mbar) : "memory");
}
__device__ __forceinline__ void mbar_wait_parity(unsigned a, unsigned phase) {
    unsigned done;
    asm volatile(
        "{\n\t.reg .pred p;\n\t"
        "mbarrier.try_wait.parity.acquire.cta.shared::cta.b64 p, [%1], %2;\n\t"
        "selp.b32 %0, 1, 0, p;\n\t}"
        : "=r"(done) : "r"(a), "r"(phase) : "memory");
    if (!done) {
        asm volatile(
            "{\n\t.reg .pred P1;\n\t"
            "WL_%=:\n\t"
            "mbarrier.try_wait.parity.acquire.cta.shared::cta.b64 P1, [%0], %1, 0x989680;\n\t"
            "@P1 bra.uni WD_%=;\n\t"
            "bra.uni WL_%=;\n\t"
            "WD_%=:\n\t}"
            :: "r"(a), "r"(phase) : "memory");
    }
}

// ---------------- prep: (B,T,K) -> [t][k][b], masked ----------------
__global__ void prep_kernel(const float* __restrict__ in, const int* __restrict__ len) {
    int idx = blockIdx.x * blockDim.x + threadIdx.x;
    if (idx >= TT*HH*BB) return;
    int b = idx & 63;
    int k = (idx >> 6) & 511;
    int t = idx >> 15;
    float v = 0.f;
    if (t < len[b]) v = in[((size_t)b*TT + t)*HH + k];
    g_xt[idx] = v;
}

// ---------------- reverse gather ----------------
__global__ void reverse_kernel(const float* __restrict__ xt, float* __restrict__ xr,
                               const int* __restrict__ len) {
    int idx = blockIdx.x * blockDim.x + threadIdx.x;
    if (idx >= TT*HH*BB) return;
    int b = idx & 63;
    int k = (idx >> 6) & 511;
    int t = idx >> 15;
    int L = len[b];
    int tp = (t < L) ? (L - 1 - t) : t;
    xr[idx] = xt[((size_t)tp*HH + k)*BB + b];
}

// ---------------- pack W_hh[k][g*512+hid] -> wt[l][(hid*5+g)][k] ----------------
__global__ void packw_kernel(const float* __restrict__ weight) {
    int idx = blockIdx.x * blockDim.x + threadIdx.x;
    if (idx >= 4*HH*G5) return;
    int col = idx % G5;
    int k   = (idx / G5) % HH;
    int l   = idx / (G5*HH);
    int hid = col & 511, g = col >> 9;
    float v = weight[(size_t)l*LAYER_W_STRIDE + WHH_OFF + (size_t)k*G5 + col];
    g_wt[(size_t)l*(G5*HH) + (size_t)((hid*5 + g) << 9) + k] = v;
}

// ---------------- xi GEMM (unchanged passing version) ----------------
__device__ __forceinline__ int bskew(int c) { return c + ((c >> 5) << 2); }

__global__ __launch_bounds__(256, 2)
void gemm_xi_kernel(const float* __restrict__ X, const float* __restrict__ W,
                    float* __restrict__ XI)
{
    __shared__ float As[8][128];
    __shared__ float Bs[8][144];
    int tid = threadIdx.x;
    int mBase = blockIdx.x * 128;
    int gBase = blockIdx.y * 128;

    float2 acc[8][4];
    #pragma unroll
    for (int i = 0; i < 8; i++)
        #pragma unroll
        for (int j = 0; j < 4; j++) acc[i][j] = make_float2(0.f, 0.f);

    int sk  = tid >> 5;
    int sc4 = (tid & 31) * 4;
    int ty8 = (tid >> 4) * 8;
    int tx8 = (tid & 15) * 8;

    int m4 = mBase + sc4;
    const float* bsrc = X + ((size_t)(m4 >> 6) * HH) * BB + (m4 & 63);
    const float* asrc = W + gBase + sc4;
    int bsw = bskew(sc4);
    int c0 = bskew(tx8), c1 = bskew(tx8 + 4);

    for (int k0 = 0; k0 < 512; k0 += 8) {
        float4 av = *(const float4*)(asrc + (size_t)(k0 + sk)*G6);
        float4 bv = *(const float4*)(bsrc + (size_t)(k0 + sk)*BB);
        *(float4*)&As[sk][sc4] = av;
        *(float4*)&Bs[sk][bsw] = bv;
        __syncthreads();
        #pragma unroll
        for (int kk = 0; kk < 8; kk++) {
            float4 a0 = *(float4*)&As[kk][ty8];
            float4 a1 = *(float4*)&As[kk][ty8+4];
            float4 b0 = *(float4*)&Bs[kk][c0];
            float4 b1 = *(float4*)&Bs[kk][c1];
            float  ar[8] = {a0.x,a0.y,a0.z,a0.w,a1.x,a1.y,a1.z,a1.w};
            float2 br[4] = {make_float2(b0.x,b0.y), make_float2(b0.z,b0.w),
                            make_float2(b1.x,b1.y), make_float2(b1.z,b1.w)};
            #pragma unroll
            for (int i = 0; i < 8; i++) {
                float2 ad = make_float2(ar[i], ar[i]);
                #pragma unroll
                for (int jp = 0; jp < 4; jp++)
                    acc[i][jp] = ffma2(ad, br[jp], acc[i][jp]);
            }
        }
        __syncthreads();
    }

    int m0 = mBase + tx8;
    int t  = m0 >> 6;
    int b0 = m0 & 63;
    #pragma unroll
    for (int i = 0; i < 8; i++) {
        float* o = XI + ((size_t)t*G6 + gBase + ty8 + i)*BB + b0;
        *(float4*)(o)     = make_float4(acc[i][0].x, acc[i][0].y, acc[i][1].x, acc[i][1].y);
        *(float4*)(o + 4) = make_float4(acc[i][2].x, acc[i][2].y, acc[i][3].x, acc[i][3].y);
    }
}

// ---------------- persistent per-layer recurrence ----------------
// 128 CTAs x 288 thr (8 FMA warps + 1 staging warp). Per-group monotonic
// counters: chunk ch of h is produced by CTA group ch (32 CTAs); the staging
// warp polls cnt[ch] and issues the cp.async.bulk for that chunk as soon as
// its producer group arrived — groups 1-3 arrival hides under FMA of
// earlier chunks. No full-barrier epoch round-trip on the critical path.
__global__ __launch_bounds__(288)
void lstm_layer_kernel(const float* __restrict__ xi_base, // [T][G6][B]
                       const float* __restrict__ wt,      // packed layer W_hh
                       const float* __restrict__ bias,    // [G5]
                       const int*   __restrict__ len,
                       float* __restrict__ hbuf0,
                       float* __restrict__ hbuf1,
                       float* __restrict__ y,             // [T][H][B]
                       int rev)
{
    extern __shared__ float smf[];
    int tid = threadIdx.x;
    int hid0 = blockIdx.x * 4;
    int grp  = blockIdx.x >> 5;          // producer group of this CTA

    unsigned smbase = smem_u32(smf);
    unsigned mbar0  = smbase + OFF_MBAR_BYTES;
    unsigned hdst0  = smbase + OFF_H * 4;

    // FMA-phase mapping (tid < 256)
    int w8 = tid >> 5;
    int bp = tid & 31;
    // output-phase mapping (tid < 256)
    int hl_o = tid >> 6;
    int b_o  = tid & 63;
    int hid_o = hid0 + (hl_o & 3);

    // one-time: weights -> smem (40KB linear) by compute threads
    if (tid < 256) {
        const float4* ws = (const float4*)(wt + (size_t)hid0 * 5 * 512);
        float4* wd = (float4*)(smf + OFF_W);
        #pragma unroll
        for (int i = 0; i < 10; i++) wd[tid + i*256] = ws[tid + i*256];
    }
    if (tid == 256) {
        #pragma unroll
        for (int c = 0; c < 4; c++) mbar_init(mbar0 + 8*c, 1);
        asm volatile("fence.proxy.async.shared::cta;" ::: "memory");
    }

    float bval[5] = {0.f, 0.f, 0.f, 0.f, 0.f};
    int L = 0;
    float xiv[6] = {0.f, 0.f, 0.f, 0.f, 0.f, 0.f};
    if (tid < 256) {
        #pragma unroll
        for (int g = 0; g < 5; g++) bval[g] = bias[g*512 + hid_o];
        L = len[b_o];
        #pragma unroll
        for (int g = 0; g < 6; g++)
            xiv[g] = __ldcs(xi_base + (size_t)(g*512 + hid_o)*BB + b_o);
    }
    float c = 0.0f;

    const float* hin  = hbuf0;
    float*       hout = hbuf1;

    __syncthreads();                      // weights + mbar init visible

    // stage step 0 (h[-1] = zeros, no producers to wait for)
    if (tid == 256) {
        #pragma unroll
        for (int ch = 0; ch < 4; ch++) {
            mbar_expect_tx(mbar0 + 8*ch, 32768u);
            bulk_g2s(hdst0 + ch*32768u, hin + ch*8192, 32768u, mbar0 + 8*ch);
        }
    }

    for (int s = 0; s < TT; s++) {
        unsigned phase = (unsigned)(s & 1);

        float2 acc[20];
        if (tid < 256) {
            #pragma unroll
            for (int q = 0; q < 20; q++) acc[q] = make_float2(0.f, 0.f);

            #pragma unroll
            for (int ch = 0; ch < 4; ch++) {
                mbar_wait_parity(mbar0 + 8*ch, phase);
                const float* shh = smf + OFF_H + ch*8192 + 2*bp;
                const float* shw = smf + OFF_W + ch*128 + w8*16;
                #pragma unroll
                for (int k4 = 0; k4 < 16; k4 += 4) {
                    int kb = (w8*16 + k4) * 64;
                    float2 hv0 = *(const float2*)(shh + kb);
                    float2 hv1 = *(const float2*)(shh + kb + 64);
                    float2 hv2 = *(const float2*)(shh + kb + 128);
                    float2 hv3 = *(const float2*)(shh + kb + 192);
                    #pragma unroll
                    for (int q = 0; q < 20; q++) {
                        float4 w4 = *(const float4*)(shw + q*512 + k4);
                        acc[q] = ffma2(hv0, make_float2(w4.x, w4.x), acc[q]);
                        acc[q] = ffma2(hv1, make_float2(w4.y, w4.y), acc[q]);
                        acc[q] = ffma2(hv2, make_float2(w4.z, w4.z), acc[q]);
                        acc[q] = ffma2(hv3, make_float2(w4.w, w4.w), acc[q]);
                    }
                }
            }

            // write partials (stride 42 avoids conflicts)
            float* rb = smf + OFF_R + (w8*32 + bp)*42;
            #pragma unroll
            for (int q = 0; q < 20; q++) *(float2*)(rb + 2*q) = acc[q];
        }
        __syncthreads();                              // sync A

        float hn = 0.f;
        if (tid < 256) {
            float gv[5];
            #pragma unroll
            for (int g = 0; g < 5; g++) gv[g] = xiv[g] + bval[g];
            const float* rbase = smf + OFF_R + (b_o >> 1)*42 + (b_o & 1);
            #pragma unroll
            for (int w2 = 0; w2 < 8; w2++) {
                const float* p = rbase + w2*32*42;
                #pragma unroll
                for (int g = 0; g < 5; g++)
                    gv[g] += p[(hl_o*5 + g)*2];
            }

            float ig = sigmoidf_(gv[0]);
            float fg = sigmoidf_(gv[1]);
            float gc = tanhf(gv[2]);
            float og = sigmoidf_(gv[3]);
            float rg = sigmoidf_(gv[4]);
            float lin = xiv[5];

            float cn;
            if (s < L) {
                cn = fg*c + ig*gc;
                hn = rg*(og*tanhf(cn)) + (1.f - rg)*lin;
            } else {
                cn = 0.f; hn = 0.f;
            }
            c = cn;
            hout[hid_o*BB + b_o] = hn;                // coalesced
        }
        __syncthreads();                              // sync B: hout done, smem h free

        int dst = rev ? ((s < L) ? (L - 1 - s) : s) : s;

        if (s != TT-1) {
            // producer arrive: this CTA's h(s) is published
            if (tid == 0)
                red_add_release_gpu(&g_cnt[grp], 1u);

            // epilogue off the critical path
            if (tid < 256) {
                y[((size_t)dst*HH + hid_o)*BB + b_o] = hn;
                const float* xs = xi_base + (size_t)(s+1)*G6*BB;
                #pragma unroll
                for (int g = 0; g < 6; g++)
                    xiv[g] = __ldcs(xs + (size_t)(g*512 + hid_o)*BB + b_o);
            }

            // staging warp: per-chunk poll + issue (source = h just written)
            if (tid == 256) {
                const float* hsrc = hout;
                unsigned target = 32u * (unsigned)(s + 1);
                #pragma unroll
                for (int ch = 0; ch < 4; ch++) {
                    while (ld_acquire_gpu(&g_cnt[ch]) < target) __nanosleep(32);
                    mbar_expect_tx(mbar0 + 8*ch, 32768u);
                    bulk_g2s(hdst0 + ch*32768u, hsrc + ch*8192, 32768u, mbar0 + 8*ch);
                }
            }
        } else if (tid < 256) {
            y[((size_t)dst*HH + hid_o)*BB + b_o] = hn;
        }

        const float* tmp = hin; hin = hout; hout = (float*)tmp;
    }
}

// ---------------- final: [t][k][b] -> (B,T,K) ----------------
__global__ void out_kernel(const float* __restrict__ xt, float* __restrict__ out) {
    int idx = blockIdx.x * blockDim.x + threadIdx.x;
    if (idx >= TT*HH*BB) return;
    int k = idx & 511;
    int t = (idx >> 9) & 255;
    int b = idx >> 17;
    out[idx] = xt[((size_t)t*HH + k)*BB + b];
}

// ---------------- launch ----------------
extern "C" void kernel_launch(void* const* d_in, const int* in_sizes, int n_in,
                              void* d_out, int out_size)
{
    const float* inputs = nullptr;
    const float* weight = nullptr;
    const float* biasp  = nullptr;
    const int*   len    = nullptr;
    for (int i = 0; i < n_in; i++) {
        switch (in_sizes[i]) {
            case TT*BB*HH:  inputs = (const float*)d_in[i]; break;  // 8388608
            case 11534336:  weight = (const float*)d_in[i]; break;
            case 4*G5:      biasp  = (const float*)d_in[i]; break;  // 10240
            case BB:        len    = (const int*)  d_in[i]; break;  // 64
        }
    }

    float *pxt, *pyt, *pxr, *pxi, *ph0, *ph1, *pwt;
    unsigned* pcnt;
    cudaGetSymbolAddress((void**)&pxt, g_xt);
    cudaGetSymbolAddress((void**)&pyt, g_yt);
    cudaGetSymbolAddress((void**)&pxr, g_xr);
    cudaGetSymbolAddress((void**)&pxi, g_xi);
    cudaGetSymbolAddress((void**)&ph0, g_h0);
    cudaGetSymbolAddress((void**)&ph1, g_h1);
    cudaGetSymbolAddress((void**)&pwt, g_wt);
    cudaGetSymbolAddress((void**)&pcnt, g_cnt);

    cudaFuncSetAttribute(lstm_layer_kernel,
                         cudaFuncAttributeMaxDynamicSharedMemorySize, SMEM_LSTM);

    prep_kernel<<<(TT*HH*BB + 255)/256, 256>>>(inputs, len);
    packw_kernel<<<(4*HH*G5 + 255)/256, 256>>>(weight);

    float* xin  = pxt;
    float* yout = pyt;
    for (int l = 0; l < 4; l++) {
        int rev = l & 1;
        const float* gsrc = xin;
        if (rev) {
            reverse_kernel<<<(TT*HH*BB + 255)/256, 256>>>(xin, pxr, len);
            gsrc = pxr;
        }
        gemm_xi_kernel<<<dim3(128, 24), 256>>>(
            gsrc, weight + (size_t)l*LAYER_W_STRIDE, pxi);
        cudaMemsetAsync(ph0, 0, (size_t)HH*BB*sizeof(float));
        cudaMemsetAsync(pcnt, 0, 4*sizeof(unsigned));
        lstm_layer_kernel<<<NCTA, 288, SMEM_LSTM>>>(
            pxi, pwt + (size_t)l*G5*HH, biasp + (size_t)l*G5,
            len, ph0, ph1, yout, rev);
        float* tmp = xin; xin = yout; yout = tmp;
    }
    out_kernel<<<(TT*HH*BB + 255)/256, 256>>>(xin, (float*)d_out);
}